// round 16
// baseline (speedup 1.0000x reference)
#include <cuda_runtime.h>
#include <cstdint>

constexpr int B = 64;
constexpr int T = 1024;
constexpr int V = 512;
constexpr int L = 128;
constexpr int EST  = 128;      // emit row stride: ratios for labels 0..127
constexpr int TPAD = T + 32;   // pad rows stay zero forever (never written)
constexpr int THREADS = 288;   // 8 producer warps + 1 consumer warp

#define FULLM  0xffffffffu
#define LOG2E  1.4426950408889634f
#define LN2    0.6931471805599453f

__device__ __align__(16) float Eexp[(size_t)B * TPAD * EST];   // ~34.6 MB, zero-init
__device__ float g_loss[B];
__device__ int   g_ctr = 0;

__device__ __forceinline__ float ex2f(float x) {
    float y; asm("ex2.approx.f32 %0, %1;" : "=f"(y) : "f"(x)); return y;
}
__device__ __forceinline__ float lg2f(float x) {
    float y; asm("lg2.approx.f32 %0, %1;" : "=f"(y) : "f"(x)); return y;
}
__device__ __forceinline__ float lse2log(float a, float b) {
    const float m  = fmaxf(a, b);
    const float mn = fminf(a, b);
    return m + lg2f(1.0f + ex2f(mn - m));
}

__global__ __launch_bounds__(THREADS, 1)
void ctc_fused(const float* __restrict__ outputs,
               const int*   __restrict__ labels,
               const int*   __restrict__ output_lengths,
               const int*   __restrict__ label_lengths,
               float* __restrict__ out) {
    __shared__ int   sctr[128];     // per-chunk completion counters (8 = ready)
    __shared__ float lb2s[T];       // per-row blank log2

    const int b    = blockIdx.x;
    const int tid  = threadIdx.x;
    const int lane = tid & 31;
    const int w    = tid >> 5;

    for (int i = tid; i < 128; i += THREADS) sctr[i] = 0;
    __syncthreads();

    const int* lb = labels + b * L;

    if (w < 8) {
        // ===================== PRODUCERS (warps 0..7) =====================
        const int c0 = __ldg(lb + 4 * lane),     c1 = __ldg(lb + 4 * lane + 1);
        const int c2 = __ldg(lb + 4 * lane + 2), c3 = __ldg(lb + 4 * lane + 3);
        const float* gbase = outputs + (size_t)b * T * V;
        float* ebase = Eexp + (size_t)b * TPAD * EST + 4 * lane;

        for (int i = 0; i < 128; i += 4) {       // 4 chunks per iteration (MLP)
            #pragma unroll
            for (int u = 0; u < 4; ++u) {
                const int r = 8 * (i + u) + w;
                const float* row = gbase + (size_t)r * V;
                const float bl = __ldg(row);
                float4 o;
                o.x = ex2f((__ldg(row + c0) - bl) * LOG2E);
                o.y = ex2f((__ldg(row + c1) - bl) * LOG2E);
                o.z = ex2f((__ldg(row + c2) - bl) * LOG2E);
                o.w = ex2f((__ldg(row + c3) - bl) * LOG2E);
                *reinterpret_cast<float4*>(ebase + (size_t)r * EST) = o;
                if (lane == 0) lb2s[r] = bl * LOG2E;
            }
            __threadfence();                     // emits + lb2s visible
            if (lane == 0) {
                atomicAdd(&sctr[i],     1);
                atomicAdd(&sctr[i + 1], 1);
                atomicAdd(&sctr[i + 2], 1);
                atomicAdd(&sctr[i + 3], 1);
            }
        }
        return;
    }

    // ===================== CONSUMER (warp 8) =====================
    const int olen = output_lengths[b];
    const int llen = label_lengths[b];
    const int tcap = olen - 1;
    const int s0g  = 2 * llen - 1;           // odd final state
    const int s1g  = 2 * llen;               // even final state (or 256)

    float s0, s1, s2, s3;                    // skip weights as 0/1 floats
    {
        const int li0 = 4 * lane;
        const int c0 = __ldg(lb + li0), c1 = __ldg(lb + li0 + 1);
        const int c2 = __ldg(lb + li0 + 2), c3 = __ldg(lb + li0 + 3);
        s0 = ((li0 > 0) && (c0 != __ldg(lb + li0 - 1))) ? 1.0f : 0.0f;
        s1 = (c1 != c0) ? 1.0f : 0.0f;
        s2 = (c2 != c1) ? 1.0f : 0.0f;
        s3 = (c3 != c2) ? 1.0f : 0.0f;
    }

    const bool o0_0 = (s0g == 8 * lane + 1), o0_1 = (s0g == 8 * lane + 3);
    const bool o0_2 = (s0g == 8 * lane + 5), o0_3 = (s0g == 8 * lane + 7);
    const bool o1_0 = (s1g == 8 * lane),     o1_1 = (s1g == 8 * lane + 2);
    const bool o1_2 = (s1g == 8 * lane + 4), o1_3 = (s1g == 8 * lane + 6);
    const bool oC   = (lane == 31) && (s1g == 256);
    const bool own0 = o0_0 || o0_1 || o0_2 || o0_3;
    const bool own1 = o1_0 || o1_1 || o1_2 || o1_3 || oC;

    const float* Eb = Eexp + (size_t)b * TPAD * EST;

    #define WAITC(CI_)                                                            \
    {                                                                             \
        int ci_ = (CI_); ci_ = (ci_ > 127) ? 127 : ci_;                           \
        if (lane == 0) {                                                          \
            while (((volatile int*)sctr)[ci_] < 8) __nanosleep(32);               \
        }                                                                         \
        __syncwarp();                                                             \
    }

    float a0=0,a1=0,a2=0,a3=0,a4=0,a5=0,a6=0,a7=0, C=0;
    int   cum = 32;
    float cap0 = 1.0f, cap1 = 1.0f;
    int   capE0 = 0, capE1 = 0;

    WAITC(0) WAITC(1) WAITC(2)
    asm volatile("fence.acq_rel.gpu;" ::: "memory");

    {   // ---- t = 0 init (scaled 2^-32) ----
        const float h  = __uint_as_float((unsigned)(127 - 32) << 23);
        const float r0 = __ldcg(Eb + 0);     // ratio(row 0, label 0)
        if (lane == 0) { a0 = h; a1 = r0 * h; }
        if (tcap == 0) {
            cap0 = o0_0 ? a1 : cap0;
            cap1 = o1_0 ? a0 : cap1;
            capE0 = cum; capE1 = cum;
        }
    }

    // triple-buffered emit registers; each buffer holds one 8-row block
    float4 elA[8], elB[8], elC[8];
    #pragma unroll
    for (int k = 0; k < 8; ++k)
        elA[k] = __ldcg((const float4*)(Eb + (size_t)(1 + k) * EST) + lane);
    #pragma unroll
    for (int k = 0; k < 8; ++k)
        elB[k] = __ldcg((const float4*)(Eb + (size_t)(9 + k) * EST) + lane);

    float b7pipe = __shfl_up_sync(FULLM, a7, 1);

    #define CTC_STEP(K_, TB_, BS0_, ELC, CAPF_)                                   \
    {                                                                             \
        const float b7n = b7pipe * (BS0_);                                        \
        const float4 e4 = ELC[K_];                                                \
        C  = C + a7;                                                              \
        const float a7n = (a7 + fmaf(s3, a5, a6)) * e4.w;                         \
        b7pipe = __shfl_up_sync(FULLM, a7n, 1);                                   \
        a6 = a6 + a5;                                                             \
        a5 = (a5 + fmaf(s2, a3, a4 )) * e4.z;                                     \
        a4 = a4 + a3;                                                             \
        a3 = (a3 + fmaf(s1, a1, a2 )) * e4.y;                                     \
        a2 = a2 + a1;                                                             \
        a1 = (a1 + fmaf(s0, b7n, a0)) * e4.x;                                     \
        a0 = a0 + b7n;                                                            \
        a7 = a7n;                                                                 \
        if (CAPF_) {                                                              \
            const bool pc  = ((TB_) + (K_) == tcap);                              \
            const bool h0  = pc && own0;                                          \
            const bool h1  = pc && own1;                                          \
            const float v0 = o0_0 ? a1 : (o0_1 ? a3 : (o0_2 ? a5 : a7));          \
            const float v1 = o1_0 ? a0 : (o1_1 ? a2 :                             \
                             (o1_2 ? a4 : (oC ? C : a6)));                        \
            cap0  = h0 ? v0  : cap0;  cap1  = h1 ? v1  : cap1;                    \
            capE0 = h0 ? cum : capE0; capE1 = h1 ? cum : capE1;                   \
        }                                                                         \
    }

    #define CTC_BLOCK(TB_, ELCN, ELN)                                             \
    {                                                                             \
        const int  cumP  = __shfl_up_sync(FULLM, cum, 1);                         \
        int        db    = cumP - cum;                                            \
        const bool adopt = (lane > 0) && (db > 40);                               \
        a0 = adopt ? 0.0f : a0;  a1 = adopt ? 0.0f : a1;                          \
        a2 = adopt ? 0.0f : a2;  a3 = adopt ? 0.0f : a3;                          \
        a4 = adopt ? 0.0f : a4;  a5 = adopt ? 0.0f : a5;                          \
        a6 = adopt ? 0.0f : a6;  a7 = adopt ? 0.0f : a7;                          \
        C  = adopt ? 0.0f : C;                                                    \
        cum = adopt ? cumP : cum;                                                 \
        db  = adopt ? 0 : db;                                                     \
        db  = (db < -126) ? -126 : db;                                            \
        const float bscale = __uint_as_float((unsigned)(127 + db) << 23);         \
        const float bs0    = (lane == 0) ? 0.0f : bscale;                         \
        b7pipe = __shfl_up_sync(FULLM, a7, 1);                                    \
        WAITC(((TB_) + 16) >> 3)                                                  \
        WAITC(((TB_) + 23) >> 3)                                                  \
        asm volatile("fence.acq_rel.gpu;" ::: "memory");                          \
        const float* rblk = Eb + (size_t)((TB_) + 16) * EST;                      \
        _Pragma("unroll")                                                         \
        for (int k_ = 0; k_ < 8; ++k_)                                            \
            ELN[k_] = __ldcg((const float4*)(rblk + k_ * EST) + lane);            \
        if ((unsigned)(tcap - (TB_)) < 8u) {                                      \
            _Pragma("unroll")                                                     \
            for (int k_ = 0; k_ < 8; ++k_)                                        \
                CTC_STEP(k_, TB_, bs0, ELCN, true)                                \
        } else {                                                                  \
            _Pragma("unroll")                                                     \
            for (int k_ = 0; k_ < 8; ++k_)                                        \
                CTC_STEP(k_, TB_, bs0, ELCN, false)                               \
        }                                                                         \
        const float mx = fmaxf(fmaxf(fmaxf(a0, a1), fmaxf(a2, a3)),               \
                               fmaxf(fmaxf(a4, a5), fmaxf(a6, fmaxf(a7, C))));    \
        const int ee   = (int)((__float_as_uint(mx) >> 23) & 0xffu);              \
        int radj = ee - 95;                                                       \
        radj = (radj < -95) ? -95 : radj;                                         \
        radj = (radj > 126) ? 126 : radj;                                         \
        const float sf = __uint_as_float((unsigned)(127 - radj) << 23);           \
        a0*=sf; a1*=sf; a2*=sf; a3*=sf; a4*=sf; a5*=sf; a6*=sf; a7*=sf; C*=sf;    \
        cum += radj;                                                              \
    }

    // ---- main: 128 blocks (t = 1..1024; t=1024 is harmless overshoot) ----
    for (int g3 = 0; g3 < 126; g3 += 3) {
        const int tb = 1 + 8 * g3;
        CTC_BLOCK(tb,      elA, elC)
        CTC_BLOCK(tb + 8,  elB, elA)
        CTC_BLOCK(tb + 16, elC, elB)
    }
    CTC_BLOCK(1009, elA, elC)   // loads pad rows (zero, never produced — safe)
    CTC_BLOCK(1017, elB, elA)
    #undef CTC_STEP
    #undef CTC_BLOCK
    #undef WAITC

    // ---- epilogue: blank-log sum from smem (deterministic) + cap gather ----
    float S = 0.0f;
    #pragma unroll 8
    for (int i = lane; i < T; i += 32)
        S += (i <= tcap) ? lb2s[i] : 0.0f;
    #pragma unroll
    for (int o = 16; o > 0; o >>= 1)
        S += __shfl_xor_sync(FULLM, S, o);

    const int src0 = s0g >> 3;
    int src1 = s1g >> 3; src1 = (src1 > 31) ? 31 : src1;
    const float f0 = __shfl_sync(FULLM, cap0, src0);
    const float f1 = __shfl_sync(FULLM, cap1, src1);
    const int   x0 = __shfl_sync(FULLM, capE0, src0);
    const int   x1 = __shfl_sync(FULLM, capE1, src1);

    if (lane == 0) {
        const float l0 = lg2f(f0) + (float)x0 + S;
        const float l1 = lg2f(f1) + (float)x1 + S;
        const float ll = lse2log(l0, l1) * LN2;
        g_loss[b] = -ll / (float)llen;
        __threadfence();
        const int old = atomicAdd(&g_ctr, 1);
        if (old == B - 1) {
            __threadfence();
            float acc = 0.0f;
            #pragma unroll 8
            for (int i = 0; i < B; ++i) acc += g_loss[i];
            *out = acc * (1.0f / (float)B);
            g_ctr = 0;   // reset for next graph replay
        }
    }
}

extern "C" void kernel_launch(void* const* d_in, const int* in_sizes, int n_in,
                              void* d_out, int out_size) {
    const float* outputs        = (const float*)d_in[0];
    const int*   labels         = (const int*)d_in[1];
    const int*   output_lengths = (const int*)d_in[2];
    const int*   label_lengths  = (const int*)d_in[3];
    float* out = (float*)d_out;

    ctc_fused<<<B, THREADS>>>(outputs, labels, output_lengths,
                              label_lengths, out);
}

// round 17
// speedup vs baseline: 1.5017x; 1.5017x over previous
#include <cuda_runtime.h>
#include <cstdint>

constexpr int B = 64;
constexpr int T = 1024;
constexpr int V = 512;
constexpr int L = 128;
constexpr int EST  = 128;      // emit row stride: ratios for labels 0..127
constexpr int TPAD = T + 32;   // pad rows stay zero forever (never written)
constexpr int NPROD = 2048;    // producer CTAs (each does 4 chunks = 32 rows)
constexpr int THREADS = 256;

#define FULLM  0xffffffffu
#define LOG2E  1.4426950408889634f
#define LN2    0.6931471805599453f

__device__ __align__(16) float Eexp[(size_t)B * TPAD * EST];   // ~34.6 MB, zero-init
__device__ float lb2arr[(size_t)B * T];                        // per-row blank log2
__device__ int   g_flags[B * 128];                             // per-chunk ready flags
__device__ float g_loss[B];
__device__ int   g_ctr = 0;

__device__ __forceinline__ float ex2f(float x) {
    float y; asm("ex2.approx.f32 %0, %1;" : "=f"(y) : "f"(x)); return y;
}
__device__ __forceinline__ float lg2f(float x) {
    float y; asm("lg2.approx.f32 %0, %1;" : "=f"(y) : "f"(x)); return y;
}
__device__ __forceinline__ float lse2log(float a, float b) {
    const float m  = fmaxf(a, b);
    const float mn = fminf(a, b);
    return m + lg2f(1.0f + ex2f(mn - m));
}

#define LDACQ(DST_, PTR_) \
    asm volatile("ld.acquire.gpu.global.s32 %0, [%1];" : "=r"(DST_) : "l"(PTR_) : "memory");

__global__ __launch_bounds__(THREADS, 1)
void ctc_ws(const float* __restrict__ outputs,
            const int*   __restrict__ labels,
            const int*   __restrict__ output_lengths,
            const int*   __restrict__ label_lengths,
            float* __restrict__ out) {
    const int tid  = threadIdx.x;
    const int lane = tid & 31;
    const int w    = tid >> 5;

    if (blockIdx.x >= 64) {
        // ===================== PRODUCERS =====================
        const int idx = blockIdx.x - 64;          // chunk-major: quad q, batch b
        const int b   = idx & 63;
        const int q   = idx >> 6;                 // 0..31
        const int cbase = q << 2;                 // chunks cbase..cbase+3

        const int* lb = labels + b * L;
        const int c0 = __ldg(lb + 4 * lane),     c1 = __ldg(lb + 4 * lane + 1);
        const int c2 = __ldg(lb + 4 * lane + 2), c3 = __ldg(lb + 4 * lane + 3);

        const float* gbase = outputs + (size_t)b * T * V;
        float* ebase = Eexp + (size_t)b * TPAD * EST + 4 * lane;

        #pragma unroll
        for (int u = 0; u < 4; ++u) {
            const int r = ((cbase + u) << 3) + w;       // row in [0,1024)
            const float* row = gbase + (size_t)r * V;
            const float bl = __ldg(row);
            float4 o;
            o.x = ex2f((__ldg(row + c0) - bl) * LOG2E);
            o.y = ex2f((__ldg(row + c1) - bl) * LOG2E);
            o.z = ex2f((__ldg(row + c2) - bl) * LOG2E);
            o.w = ex2f((__ldg(row + c3) - bl) * LOG2E);
            *reinterpret_cast<float4*>(ebase + (size_t)r * EST) = o;
            if (lane == 0) lb2arr[(size_t)b * T + r] = bl * LOG2E;
        }
        __threadfence();
        __syncthreads();
        if (tid < 4) {
            int* fp = g_flags + (b << 7) + cbase + tid;
            asm volatile("st.release.gpu.global.s32 [%0], %1;"
                         :: "l"(fp), "r"(1) : "memory");
        }
        return;
    }

    // ===================== CONSUMER (warp 0 of blocks 0..63) =====================
    if (w != 0) return;

    const int b    = blockIdx.x;
    const int olen = output_lengths[b];
    const int llen = label_lengths[b];
    const int tcap = olen - 1;
    const int s0g  = 2 * llen - 1;           // odd final state
    const int s1g  = 2 * llen;               // even final state (or 256)

    const int* lb = labels + b * L;
    float s0, s1, s2, s3;                    // skip weights as 0/1 floats
    {
        const int li0 = 4 * lane;
        const int c0 = __ldg(lb + li0), c1 = __ldg(lb + li0 + 1);
        const int c2 = __ldg(lb + li0 + 2), c3 = __ldg(lb + li0 + 3);
        s0 = ((li0 > 0) && (c0 != __ldg(lb + li0 - 1))) ? 1.0f : 0.0f;
        s1 = (c1 != c0) ? 1.0f : 0.0f;
        s2 = (c2 != c1) ? 1.0f : 0.0f;
        s3 = (c3 != c2) ? 1.0f : 0.0f;
    }

    const bool o0_0 = (s0g == 8 * lane + 1), o0_1 = (s0g == 8 * lane + 3);
    const bool o0_2 = (s0g == 8 * lane + 5), o0_3 = (s0g == 8 * lane + 7);
    const bool o1_0 = (s1g == 8 * lane),     o1_1 = (s1g == 8 * lane + 2);
    const bool o1_2 = (s1g == 8 * lane + 4), o1_3 = (s1g == 8 * lane + 6);
    const bool oC   = (lane == 31) && (s1g == 256);
    const bool own0 = o0_0 || o0_1 || o0_2 || o0_3;
    const bool own1 = o1_0 || o1_1 || o1_2 || o1_3 || oC;

    const float* Eb    = Eexp + (size_t)b * TPAD * EST;
    const int*   fbase = g_flags + (b << 7);

    // prologue: wait chunks 0,1; issue flag read for chunk 2
    int fv;
    LDACQ(fv, fbase + 0)
    while (fv == 0) { __nanosleep(128); LDACQ(fv, fbase + 0) }
    LDACQ(fv, fbase + 1)
    while (fv == 0) { __nanosleep(128); LDACQ(fv, fbase + 1) }

    float4 elA[8], elB[8], elC[8];
    #pragma unroll
    for (int k = 0; k < 8; ++k)
        elA[k] = __ldcg((const float4*)(Eb + (size_t)k * EST) + lane);       // chunk 0
    #pragma unroll
    for (int k = 0; k < 8; ++k)
        elB[k] = __ldcg((const float4*)(Eb + (size_t)(8 + k) * EST) + lane); // chunk 1
    LDACQ(fv, fbase + 2)

    // ---- t = 0 init (scaled 2^-32) ----
    float a0=0,a1=0,a2=0,a3=0,a4=0,a5=0,a6=0,a7=0, C=0;
    int   cum = 32;
    float cap0 = 1.0f, cap1 = 1.0f;
    int   capE0 = 0, capE1 = 0;
    {
        const float h  = __uint_as_float((unsigned)(127 - 32) << 23);
        const float r0 = __ldcg(Eb + 0);     // ratio(row 0, label 0)
        if (lane == 0) { a0 = h; a1 = r0 * h; }
        if (tcap == 0) {
            cap0 = o0_0 ? a1 : cap0;
            cap1 = o1_0 ? a0 : cap1;
            capE0 = cum; capE1 = cum;
        }
    }
    float b7pipe = __shfl_up_sync(FULLM, a7, 1);

    #define CTC_STEP(K_, TB_, BS0_, ELC, CAPF_)                                   \
    {                                                                             \
        const float b7n = b7pipe * (BS0_);                                        \
        const float4 e4 = ELC[K_];                                                \
        C  = C + a7;                                                              \
        const float a7n = (a7 + fmaf(s3, a5, a6)) * e4.w;                         \
        b7pipe = __shfl_up_sync(FULLM, a7n, 1);                                   \
        a6 = a6 + a5;                                                             \
        a5 = (a5 + fmaf(s2, a3, a4 )) * e4.z;                                     \
        a4 = a4 + a3;                                                             \
        a3 = (a3 + fmaf(s1, a1, a2 )) * e4.y;                                     \
        a2 = a2 + a1;                                                             \
        a1 = (a1 + fmaf(s0, b7n, a0)) * e4.x;                                     \
        a0 = a0 + b7n;                                                            \
        a7 = a7n;                                                                 \
        if (CAPF_) {                                                              \
            const bool pc  = ((TB_) + (K_) == tcap);                              \
            const bool h0  = pc && own0;                                          \
            const bool h1  = pc && own1;                                          \
            const float v0 = o0_0 ? a1 : (o0_1 ? a3 : (o0_2 ? a5 : a7));          \
            const float v1 = o1_0 ? a0 : (o1_1 ? a2 :                             \
                             (o1_2 ? a4 : (oC ? C : a6)));                        \
            cap0  = h0 ? v0  : cap0;  cap1  = h1 ? v1  : cap1;                    \
            capE0 = h0 ? cum : capE0; capE1 = h1 ? cum : capE1;                   \
        }                                                                         \
    }

    // block g: steps t = 8g..8g+7 (K0_=1 for g=0), consume ELCN, load chunk g+2
    #define CTC_BLOCK(G_, K0_, ELCN, ELN)                                         \
    {                                                                             \
        const int  cumP  = __shfl_up_sync(FULLM, cum, 1);                         \
        int        db    = cumP - cum;                                            \
        const bool adopt = (lane > 0) && (db > 40);                               \
        a0 = adopt ? 0.0f : a0;  a1 = adopt ? 0.0f : a1;                          \
        a2 = adopt ? 0.0f : a2;  a3 = adopt ? 0.0f : a3;                          \
        a4 = adopt ? 0.0f : a4;  a5 = adopt ? 0.0f : a5;                          \
        a6 = adopt ? 0.0f : a6;  a7 = adopt ? 0.0f : a7;                          \
        C  = adopt ? 0.0f : C;                                                    \
        cum = adopt ? cumP : cum;                                                 \
        db  = adopt ? 0 : db;                                                     \
        db  = (db < -126) ? -126 : db;                                            \
        const float bscale = __uint_as_float((unsigned)(127 + db) << 23);         \
        const float bs0    = (lane == 0) ? 0.0f : bscale;                         \
        b7pipe = __shfl_up_sync(FULLM, a7, 1);                                    \
        if (fv == 0) {                                                            \
            const int* fp_ = fbase + (((G_) + 2 > 127) ? 127 : (G_) + 2);         \
            do { __nanosleep(64); LDACQ(fv, fp_) } while (fv == 0);               \
        }                                                                         \
        const float* rblk = Eb + (size_t)(((G_) + 2) << 3) * EST;                 \
        _Pragma("unroll")                                                         \
        for (int k_ = 0; k_ < 8; ++k_)                                            \
            ELN[k_] = __ldcg((const float4*)(rblk + (size_t)k_ * EST) + lane);    \
        {                                                                         \
            const int* fp_ = fbase + (((G_) + 3 > 127) ? 127 : (G_) + 3);         \
            LDACQ(fv, fp_)                                                        \
        }                                                                         \
        const int tb_ = (G_) << 3;                                                \
        if ((unsigned)(tcap - tb_) < 8u) {                                        \
            _Pragma("unroll")                                                     \
            for (int k_ = K0_; k_ < 8; ++k_) CTC_STEP(k_, tb_, bs0, ELCN, true)   \
        } else {                                                                  \
            _Pragma("unroll")                                                     \
            for (int k_ = K0_; k_ < 8; ++k_) CTC_STEP(k_, tb_, bs0, ELCN, false)  \
        }                                                                         \
        const float mx = fmaxf(fmaxf(fmaxf(a0, a1), fmaxf(a2, a3)),               \
                               fmaxf(fmaxf(a4, a5), fmaxf(a6, fmaxf(a7, C))));    \
        const int ee   = (int)((__float_as_uint(mx) >> 23) & 0xffu);              \
        int radj = ee - 95;                                                       \
        radj = (radj < -95) ? -95 : radj;                                         \
        radj = (radj > 126) ? 126 : radj;                                         \
        const float sf = __uint_as_float((unsigned)(127 - radj) << 23);           \
        a0*=sf; a1*=sf; a2*=sf; a3*=sf; a4*=sf; a5*=sf; a6*=sf; a7*=sf; C*=sf;    \
        cum += radj;                                                              \
    }

    // ---- 128 blocks: t = 0..1023 exactly ----
    CTC_BLOCK(0, 1, elA, elC)
    for (int gg = 1; gg < 127; gg += 3) {
        CTC_BLOCK(gg,     0, elB, elA)
        CTC_BLOCK(gg + 1, 0, elC, elB)
        CTC_BLOCK(gg + 2, 0, elA, elC)
    }
    CTC_BLOCK(127, 0, elB, elA)
    #undef CTC_STEP
    #undef CTC_BLOCK

    // ---- epilogue: blank-log sum (deterministic) + cap gather via shfl ----
    float S = 0.0f;
    {
        const float* lbp = lb2arr + (size_t)b * T;
        #pragma unroll 8
        for (int i = lane; i < T; i += 32)
            S += (i <= tcap) ? __ldcg(lbp + i) : 0.0f;
        #pragma unroll
        for (int o = 16; o > 0; o >>= 1)
            S += __shfl_xor_sync(FULLM, S, o);
    }

    const int src0 = s0g >> 3;
    int src1 = s1g >> 3; src1 = (src1 > 31) ? 31 : src1;
    const float f0 = __shfl_sync(FULLM, cap0, src0);
    const float f1 = __shfl_sync(FULLM, cap1, src1);
    const int   x0 = __shfl_sync(FULLM, capE0, src0);
    const int   x1 = __shfl_sync(FULLM, capE1, src1);

    if (lane == 0) {
        const float l0 = lg2f(f0) + (float)x0 + S;
        const float l1 = lg2f(f1) + (float)x1 + S;
        const float ll = lse2log(l0, l1) * LN2;
        g_loss[b] = -ll / (float)llen;
        __threadfence();
        const int old = atomicAdd(&g_ctr, 1);
        if (old == B - 1) {
            __threadfence();
            float acc = 0.0f;
            #pragma unroll 8
            for (int i = 0; i < B; ++i) acc += g_loss[i];
            *out = acc * (1.0f / (float)B);
            g_ctr = 0;   // reset for next graph replay
        }
    }
}

extern "C" void kernel_launch(void* const* d_in, const int* in_sizes, int n_in,
                              void* d_out, int out_size) {
    const float* outputs        = (const float*)d_in[0];
    const int*   labels         = (const int*)d_in[1];
    const int*   output_lengths = (const int*)d_in[2];
    const int*   label_lengths  = (const int*)d_in[3];
    float* out = (float*)d_out;

    ctc_ws<<<64 + NPROD, THREADS>>>(outputs, labels, output_lengths,
                                    label_lengths, out);
}